// round 16
// baseline (speedup 1.0000x reference)
#include <cuda_runtime.h>
#include <cuda_fp16.h>
#include <math.h>
#include <stdint.h>

#define SEQ 2048
#define DM 512
#define NH 8
#define DH 64
#define DFF 2048
#define BATCH 4
#define ROWS (BATCH * SEQ)   // 8192

// ---------------- device scratch (no allocation allowed) -------------------
__device__ __half g_qkvh[(size_t)ROWS * 3 * DM];
__device__ float g_d[(size_t)ROWS * DM];
__device__ __half g_xh[(size_t)ROWS * DM];
__device__ __half g_oh[(size_t)ROWS * DM];
__device__ __half g_hh[(size_t)ROWS * DFF];
#define W_TOTAL 6291456
__device__ __half g_wh[W_TOTAL];
#define OFF_QKV 0
#define OFF_OUT (2 * 1536 * 512)
#define OFF_W1  (OFF_OUT + 2 * 512 * 512)
#define OFF_W2  (OFF_W1 + 2 * 2048 * 512)

// ---------------------------------------------------------------------------
// helpers
// ---------------------------------------------------------------------------
__device__ __forceinline__ void cp16(uint32_t saddr, const void* g) {
    asm volatile("cp.async.cg.shared.global [%0], [%1], 16;" :: "r"(saddr), "l"(g));
}
__device__ __forceinline__ void cp16z(uint32_t saddr, const void* g, int sz) {
    asm volatile("cp.async.cg.shared.global [%0], [%1], 16, %2;"
                 :: "r"(saddr), "l"(g), "r"(sz));
}
__device__ __forceinline__ void ldsm_x4(uint32_t* r, uint32_t a) {
    asm volatile("ldmatrix.sync.aligned.m8n8.x4.shared.b16 {%0,%1,%2,%3}, [%4];"
                 : "=r"(r[0]), "=r"(r[1]), "=r"(r[2]), "=r"(r[3]) : "r"(a));
}
__device__ __forceinline__ void ldsm_x4_t(uint32_t* r, uint32_t a) {
    asm volatile("ldmatrix.sync.aligned.m8n8.x4.trans.shared.b16 {%0,%1,%2,%3}, [%4];"
                 : "=r"(r[0]), "=r"(r[1]), "=r"(r[2]), "=r"(r[3]) : "r"(a));
}
__device__ __forceinline__ void mma_f16(float* d, const uint32_t* a, const uint32_t* b) {
    asm volatile("mma.sync.aligned.m16n8k16.row.col.f32.f16.f16.f32 "
                 "{%0,%1,%2,%3}, {%4,%5,%6,%7}, {%8,%9}, {%0,%1,%2,%3};"
                 : "+f"(d[0]), "+f"(d[1]), "+f"(d[2]), "+f"(d[3])
                 : "r"(a[0]), "r"(a[1]), "r"(a[2]), "r"(a[3]), "r"(b[0]), "r"(b[1]));
}
#define SWZ(bo) ((bo) ^ (((bo) >> 3) & 0x70))

// ---------------------------------------------------------------------------
// conversion kernels
// ---------------------------------------------------------------------------
__global__ void conv_all(const float* __restrict__ qkv_w, const float* __restrict__ out_w,
                         const float* __restrict__ w1, const float* __restrict__ w2,
                         __half* __restrict__ dst) {
    const int i = blockIdx.x * blockDim.x + threadIdx.x;
    if (i >= W_TOTAL / 4) return;
    const int e = i * 4;
    const float* src;
    int local;
    if (e < OFF_OUT)      { src = qkv_w; local = e; }
    else if (e < OFF_W1)  { src = out_w; local = e - OFF_OUT; }
    else if (e < OFF_W2)  { src = w1;    local = e - OFF_W1; }
    else                  { src = w2;    local = e - OFF_W2; }
    const float4 v = *(const float4*)(src + local);
    ((__half2*)dst)[2 * i]     = __floats2half2_rn(v.x, v.y);
    ((__half2*)dst)[2 * i + 1] = __floats2half2_rn(v.z, v.w);
}

__global__ void copy_conv(const float* __restrict__ src, float* __restrict__ x,
                          __half* __restrict__ xh, int n4) {
    const int i = blockIdx.x * blockDim.x + threadIdx.x;
    if (i >= n4) return;
    const float4 v = ((const float4*)src)[i];
    ((float4*)x)[i] = v;
    ((__half2*)xh)[2 * i]     = __floats2half2_rn(v.x, v.y);
    ((__half2*)xh)[2 * i + 1] = __floats2half2_rn(v.z, v.w);
}

// ---------------------------------------------------------------------------
// GEMM (unchanged): plain fp16, 128x128 block tile, BK=64, SW128, 128 thr.
// ---------------------------------------------------------------------------
#define PLANEB 16384
#define BUFB (2 * PLANEB)
#define SMEMB (2 * BUFB)

template<int RELU, int HALF_OUT, int K, int N>
__global__ __launch_bounds__(128)
void gemm_tc(const __half* __restrict__ Xh, const __half* __restrict__ Wh,
             const float* __restrict__ bias, float* __restrict__ Yf,
             __half* __restrict__ Yh) {
    extern __shared__ __align__(1024) char smc[];
    const uint32_t sb = (uint32_t)__cvta_generic_to_shared(smc);

    const int tid = threadIdx.x;
    const int lane = tid & 31, warp = tid >> 5;
    const int wm = warp & 1, wn = warp >> 1;
    const int g = lane >> 2, tig = lane & 3;
    const int m0 = blockIdx.y * 128, n0 = blockIdx.x * 128;

    float acc[4][8][4] = {};
    constexpr int KT = K >> 6;

    const int row0 = tid >> 3, ch = tid & 7;
    const __half* gp0 = Xh + (size_t)(m0 + row0) * K + ch * 8;
    const __half* gp1 = Wh + (size_t)(n0 + row0) * K + ch * 8;
    const uint32_t srow = SWZ((uint32_t)(row0 * 128 + ch * 16));

    const int lrow = lane & 15;
    const uint32_t kbase = ((uint32_t)((lane >> 4) << 4)) ^ ((uint32_t)((lrow & 7) << 4));
    const uint32_t aoff = sb + (uint32_t)((wm * 64 + lrow) * 128);
    const uint32_t boff = sb + (uint32_t)((wn * 64 + lrow) * 128) + (uint32_t)PLANEB;

#define STAGE2(SBUF) do {                                                      \
    _Pragma("unroll")                                                          \
    for (int r_ = 0; r_ < 8; r_++) {                                           \
        cp16((SBUF) + srow + r_ * 2048,          gp0 + r_ * 16 * K);           \
        cp16((SBUF) + PLANEB + srow + r_ * 2048, gp1 + r_ * 16 * K);           \
    }                                                                          \
    asm volatile("cp.async.commit_group;");                                    \
    gp0 += 64; gp1 += 64;                                                      \
} while (0)

#define KTILE(BOFS) do {                                                       \
    _Pragma("unroll")                                                          \
    for (int ks = 0; ks < 4; ks++) {                                           \
        const uint32_t kq = ((uint32_t)(ks * 32)) ^ kbase;                     \
        uint32_t ah[4][4], bh[8][2];                                           \
        _Pragma("unroll")                                                      \
        for (int i = 0; i < 4; i++)                                            \
            ldsm_x4(ah[i], aoff + (BOFS) + i * 2048 + kq);                     \
        _Pragma("unroll")                                                      \
        for (int jp = 0; jp < 4; jp++) {                                       \
            uint32_t th[4];                                                    \
            ldsm_x4(th, boff + (BOFS) + jp * 2048 + kq);                       \
            bh[jp * 2][0] = th[0]; bh[jp * 2 + 1][0] = th[1];                  \
            bh[jp * 2][1] = th[2]; bh[jp * 2 + 1][1] = th[3];                  \
        }                                                                      \
        _Pragma("unroll")                                                      \
        for (int i = 0; i < 4; i++)                                            \
            _Pragma("unroll")                                                  \
            for (int j = 0; j < 8; j++)                                        \
                mma_f16(acc[i][j], ah[i], bh[j]);                              \
    }                                                                          \
} while (0)

    STAGE2(sb);

    #pragma unroll 1
    for (int kt = 0; kt < KT; kt += 2) {
        asm volatile("cp.async.wait_group 0;");
        __syncthreads();
        if (kt + 1 < KT) STAGE2(sb + BUFB);
        KTILE(0u);

        asm volatile("cp.async.wait_group 0;");
        __syncthreads();
        if (kt + 2 < KT) STAGE2(sb);
        KTILE((uint32_t)BUFB);
    }
#undef STAGE2
#undef KTILE

    #pragma unroll
    for (int i = 0; i < 4; i++) {
        const int row0e = m0 + wm * 64 + i * 16 + g;
        #pragma unroll
        for (int j = 0; j < 8; j++) {
            const int col = n0 + wn * 64 + j * 8 + 2 * tig;
            const float2 bv = *(const float2*)(bias + col);
            float2 v0 = { acc[i][j][0] + bv.x, acc[i][j][1] + bv.y };
            float2 v1 = { acc[i][j][2] + bv.x, acc[i][j][3] + bv.y };
            if (RELU) {
                v0.x = fmaxf(v0.x, 0.f); v0.y = fmaxf(v0.y, 0.f);
                v1.x = fmaxf(v1.x, 0.f); v1.y = fmaxf(v1.y, 0.f);
            }
            if (HALF_OUT) {
                *(__half2*)(Yh + (size_t)row0e * N + col) = __floats2half2_rn(v0.x, v0.y);
                *(__half2*)(Yh + (size_t)(row0e + 8) * N + col) = __floats2half2_rn(v1.x, v1.y);
            } else {
                *(float2*)(Yf + (size_t)row0e * N + col) = v0;
                *(float2*)(Yf + (size_t)(row0e + 8) * N + col) = v1;
            }
        }
    }
}

// ---------------------------------------------------------------------------
// Tensor-core log-sparse attention v4: 64 queries/block (same 128-row K/V
// window), 256 threads. Warps: 4 M-groups x 2 K-col groups.
// ---------------------------------------------------------------------------
#define ATT_QS  0            // [64][64] half SW128 (8 KB)
#define ATT_KS  8192         // [128][64] half SW128 (16 KB)
#define ATT_VS  24576        // [128][64] half SW128 (16 KB)
#define ATT_PS  40960        // 2 chunks x [64][64] half SW128 (16 KB)
#define ATT_OEX 57344        // float[64][64] (16 KB)
#define ATT_MX  73728        // float[64][2]
#define ATT_SM  74240        // float[64][2]
#define ATT_EXM 74752        // float[64]
#define ATT_EXS 75008        // float[64]
#define ATT_EXP 75264        // float[64][4]
#define ATT_SMEM 76288

__global__ __launch_bounds__(256)
void attn_mma(const __half* __restrict__ qkv, __half* __restrict__ oh) {
    extern __shared__ __align__(1024) char smc[];
    const uint32_t sb = (uint32_t)__cvta_generic_to_shared(smc);

    const int q0 = blockIdx.x * 64;
    const int h = blockIdx.y, b = blockIdx.z;
    const int tid = threadIdx.x, lane = tid & 31, warp = tid >> 5;
    const int wq = warp & 3, wk = warp >> 2;
    const int g = lane >> 2, tig = lane & 3, lrow = lane & 15;

    const __half* base = qkv + (size_t)(b * SEQ) * 1536;

    // ---- async staging: Q (2 chunks), K (4), V (4) per thread ----
    {
        const int row = tid >> 3, ch = tid & 7;
        #pragma unroll
        for (int r_ = 0; r_ < 2; r_++) {
            const int qr = row + r_ * 32;
            cp16(sb + ATT_QS + SWZ((uint32_t)(qr * 128 + ch * 16)),
                 base + (size_t)(q0 + qr) * 1536 + h * 64 + ch * 8);
        }
        #pragma unroll
        for (int r_ = 0; r_ < 4; r_++) {
            const int rr = row + r_ * 32;
            const int j = q0 - 64 + rr;
            const int valid = (j >= 0) ? 16 : 0;
            const size_t jc = (size_t)(valid ? j : 0);
            const uint32_t so = SWZ((uint32_t)(rr * 128 + ch * 16));
            cp16z(sb + ATT_KS + so, base + jc * 1536 + 512 + h * 64 + ch * 8, valid);
            cp16z(sb + ATT_VS + so, base + jc * 1536 + 1024 + h * 64 + ch * 8, valid);
        }
        asm volatile("cp.async.commit_group;");
    }

    // ---- extras raw scores from gmem (8 queries per warp) ----
    {
        float* EXM = (float*)(smc + ATT_EXM);
        float* EXPS = (float*)(smc + ATT_EXP);
        const int te = lane >> 3, g8 = lane & 7;
        #pragma unroll
        for (int c = 0; c < 8; c++) {
            const int qi = warp * 8 + c;
            const int i = q0 + qi;
            const int ne = (i >= 128) + (i >= 256) + (i >= 512) + (i >= 1024);
            float pt = 0.f;
            if (te < ne) {
                const int j = i - (128 << te);
                const uint4 kraw = *(const uint4*)(base + (size_t)j * 1536 + 512 + h * 64 + g8 * 8);
                const uint4 qraw = *(const uint4*)(base + (size_t)i * 1536 + h * 64 + g8 * 8);
                const __half2* k2 = (const __half2*)&kraw;
                const __half2* q2 = (const __half2*)&qraw;
                #pragma unroll
                for (int u = 0; u < 4; u++) {
                    const float2 kf = __half22float2(k2[u]);
                    const float2 qf = __half22float2(q2[u]);
                    pt += qf.x * kf.x + qf.y * kf.y;
                }
            }
            pt += __shfl_xor_sync(~0u, pt, 1);
            pt += __shfl_xor_sync(~0u, pt, 2);
            pt += __shfl_xor_sync(~0u, pt, 4);
            pt *= 0.125f;
            const float p0 = __shfl_sync(~0u, pt, 0);
            const float p1 = __shfl_sync(~0u, pt, 8);
            const float p2 = __shfl_sync(~0u, pt, 16);
            const float p3 = __shfl_sync(~0u, pt, 24);
            float mex = -INFINITY;
            if (ne > 0) mex = p0;
            if (ne > 1) mex = fmaxf(mex, p1);
            if (ne > 2) mex = fmaxf(mex, p2);
            if (ne > 3) mex = fmaxf(mex, p3);
            if (lane == 0) {
                EXM[qi] = mex;
                EXPS[qi * 4 + 0] = p0; EXPS[qi * 4 + 1] = p1;
                EXPS[qi * 4 + 2] = p2; EXPS[qi * 4 + 3] = p3;
            }
        }
    }
    asm volatile("cp.async.wait_group 0;");
    __syncthreads();

    // ---- S = Q @ K^T (window 64x128) ----
    float S[8][4] = {};
    const uint32_t kbase = ((uint32_t)((lane >> 4) << 4)) ^ ((uint32_t)((lrow & 7) << 4));
    {
        const uint32_t qa = sb + ATT_QS + (uint32_t)((wq * 16 + lrow) * 128);
        const uint32_t kb = sb + ATT_KS + (uint32_t)((wk * 64 + lrow) * 128);
        #pragma unroll
        for (int ks = 0; ks < 4; ks++) {
            const uint32_t kq = ((uint32_t)(ks * 32)) ^ kbase;
            uint32_t A[4], bh[8][2];
            ldsm_x4(A, qa + kq);
            #pragma unroll
            for (int jp = 0; jp < 4; jp++) {
                uint32_t th[4];
                ldsm_x4(th, kb + jp * 2048 + kq);
                bh[jp * 2][0] = th[0]; bh[jp * 2 + 1][0] = th[1];
                bh[jp * 2][1] = th[2]; bh[jp * 2 + 1][1] = th[3];
            }
            #pragma unroll
            for (int j = 0; j < 8; j++) mma_f16(S[j], A, bh[j]);
        }
    }

    // ---- mask + scale + partial row max ----
    const int r0 = wq * 16 + g, r1 = r0 + 8;
    const int cmin = 64 - q0;
    float m0 = -INFINITY, m1 = -INFINITY;
    #pragma unroll
    for (int j = 0; j < 8; j++) {
        const int col0 = wk * 64 + j * 8 + 2 * tig;
        const int col1 = col0 + 1;
        S[j][0] = (col0 >= r0 && col0 <= r0 + 64 && col0 >= cmin) ? S[j][0] * 0.125f : -INFINITY;
        S[j][1] = (col1 >= r0 && col1 <= r0 + 64 && col1 >= cmin) ? S[j][1] * 0.125f : -INFINITY;
        S[j][2] = (col0 >= r1 && col0 <= r1 + 64 && col0 >= cmin) ? S[j][2] * 0.125f : -INFINITY;
        S[j][3] = (col1 >= r1 && col1 <= r1 + 64 && col1 >= cmin) ? S[j][3] * 0.125f : -INFINITY;
        m0 = fmaxf(m0, fmaxf(S[j][0], S[j][1]));
        m1 = fmaxf(m1, fmaxf(S[j][2], S[j][3]));
    }
    m0 = fmaxf(m0, __shfl_xor_sync(~0u, m0, 1)); m0 = fmaxf(m0, __shfl_xor_sync(~0u, m0, 2));
    m1 = fmaxf(m1, __shfl_xor_sync(~0u, m1, 1)); m1 = fmaxf(m1, __shfl_xor_sync(~0u, m1, 2));
    {
        float* MX = (float*)(smc + ATT_MX);
        if (tig == 0) { MX[r0 * 2 + wk] = m0; MX[r1 * 2 + wk] = m1; }
    }
    __syncthreads();

    // ---- final row max, exp, partial sums, store P; extras exp ----
    {
        float* MX = (float*)(smc + ATT_MX);
        float* SM = (float*)(smc + ATT_SM);
        float* EXM = (float*)(smc + ATT_EXM);
        const float mxf0 = fmaxf(fmaxf(MX[r0 * 2], MX[r0 * 2 + 1]), EXM[r0]);
        const float mxf1 = fmaxf(fmaxf(MX[r1 * 2], MX[r1 * 2 + 1]), EXM[r1]);
        float s0 = 0.f, s1 = 0.f;
        #pragma unroll
        for (int j = 0; j < 8; j++) {
            const float e0 = __expf(S[j][0] - mxf0), e1 = __expf(S[j][1] - mxf0);
            const float e2 = __expf(S[j][2] - mxf1), e3 = __expf(S[j][3] - mxf1);
            s0 += e0 + e1; s1 += e2 + e3;
            const int col0 = wk * 64 + j * 8 + 2 * tig;
            char* ps = smc + ATT_PS + (col0 >> 6) * 8192;
            const int kc2 = (col0 & 63) * 2;
            *(__half2*)(ps + SWZ((uint32_t)(r0 * 128 + kc2))) = __floats2half2_rn(e0, e1);
            *(__half2*)(ps + SWZ((uint32_t)(r1 * 128 + kc2))) = __floats2half2_rn(e2, e3);
        }
        s0 += __shfl_xor_sync(~0u, s0, 1); s0 += __shfl_xor_sync(~0u, s0, 2);
        s1 += __shfl_xor_sync(~0u, s1, 1); s1 += __shfl_xor_sync(~0u, s1, 2);
        if (tig == 0) { SM[r0 * 2 + wk] = s0; SM[r1 * 2 + wk] = s1; }

        float* EXS = (float*)(smc + ATT_EXS);
        float* EXPS = (float*)(smc + ATT_EXP);
        #pragma unroll
        for (int c = 0; c < 8; c++) {
            const int qi = warp * 8 + c;
            const int i = q0 + qi;
            const int ne = (i >= 128) + (i >= 256) + (i >= 512) + (i >= 1024);
            const float mxfq = fmaxf(fmaxf(MX[qi * 2], MX[qi * 2 + 1]), EXM[qi]);
            float e = 0.f;
            if (lane < 4) {
                e = (lane < ne) ? __expf(EXPS[qi * 4 + lane] - mxfq) : 0.f;
                EXPS[qi * 4 + lane] = e;
            }
            e += __shfl_xor_sync(~0u, e, 1);
            e += __shfl_xor_sync(~0u, e, 2);
            if (lane == 0) EXS[qi] = e;
        }
    }
    __syncthreads();

    // ---- extras output Oex ----
    {
        float* OEX = (float*)(smc + ATT_OEX);
        float* EXPS = (float*)(smc + ATT_EXP);
        #pragma unroll
        for (int c = 0; c < 8; c++) {
            const int qi = warp * 8 + c;
            const int i = q0 + qi;
            const int ne = (i >= 128) + (i >= 256) + (i >= 512) + (i >= 1024);
            float2 a = {0.f, 0.f};
            #pragma unroll
            for (int t = 0; t < 4; t++) {
                if (t < ne) {
                    const int j = i - (128 << t);
                    const float2 vf = __half22float2(
                        *(const __half2*)(base + (size_t)j * 1536 + 1024 + h * 64 + 2 * lane));
                    const float wgt = EXPS[qi * 4 + t];
                    a.x += wgt * vf.x;
                    a.y += wgt * vf.y;
                }
            }
            *(float2*)(OEX + qi * 64 + 2 * lane) = a;
        }
    }
    // ---- O = P @ V ----
    float O[4][4] = {};
    {
        const uint32_t pa = sb + ATT_PS + (uint32_t)((wq * 16 + lrow) * 128);
        const uint32_t vb = sb + ATT_VS + (uint32_t)(lrow * 128);
        const uint32_t lhi = (uint32_t)((lane >> 4) << 4);
        const uint32_t lxr = (uint32_t)((lrow & 7) << 4);
        #pragma unroll
        for (int ks = 0; ks < 8; ks++) {
            uint32_t A[4];
            const uint32_t kq = ((uint32_t)((ks & 3) * 32)) ^ kbase;
            ldsm_x4(A, pa + (ks >> 2) * 8192 + kq);
            #pragma unroll
            for (int jg = 0; jg < 2; jg++) {
                uint32_t th[4];
                const uint32_t vdim = ((uint32_t)(wk * 64 + jg * 32) + lhi) ^ lxr;
                ldsm_x4_t(th, vb + ks * 2048 + vdim);
                uint32_t B0[2] = { th[0], th[1] };
                uint32_t B1[2] = { th[2], th[3] };
                mma_f16(O[jg * 2], A, B0);
                mma_f16(O[jg * 2 + 1], A, B1);
            }
        }
    }
    __syncthreads();

    // ---- epilogue: O = (PV + Oex) / rowsum ----
    {
        float* SM = (float*)(smc + ATT_SM);
        float* EXS = (float*)(smc + ATT_EXS);
        float* OEX = (float*)(smc + ATT_OEX);
        const float inv0 = 1.f / (SM[r0 * 2] + SM[r0 * 2 + 1] + EXS[r0]);
        const float inv1 = 1.f / (SM[r1 * 2] + SM[r1 * 2 + 1] + EXS[r1]);
        #pragma unroll
        for (int j = 0; j < 4; j++) {
            const int col0 = wk * 32 + j * 8 + 2 * tig;
            const float2 ex0 = *(const float2*)(OEX + r0 * 64 + col0);
            const float2 ex1 = *(const float2*)(OEX + r1 * 64 + col0);
            const __half2 h0 = __floats2half2_rn((O[j][0] + ex0.x) * inv0,
                                                 (O[j][1] + ex0.y) * inv0);
            const __half2 h1 = __floats2half2_rn((O[j][2] + ex1.x) * inv1,
                                                 (O[j][3] + ex1.y) * inv1);
            *(__half2*)(oh + (size_t)(b * SEQ + q0 + r0) * DM + h * 64 + col0) = h0;
            *(__half2*)(oh + (size_t)(b * SEQ + q0 + r1) * DM + h * 64 + col0) = h1;
        }
    }
}

// ---------------------------------------------------------------------------
// x = LayerNorm(x + d) * scale + bias; emits fp16 copy. 2 rows per block.
// Threads 0-127 own row 2*blk, threads 128-255 own row 2*blk+1.
// ---------------------------------------------------------------------------
__global__ __launch_bounds__(256)
void add_ln_kernel(float* __restrict__ x, const float* __restrict__ o,
                   const float* __restrict__ sc, const float* __restrict__ bi,
                   __half* __restrict__ xh) {
    const int half = threadIdx.x >> 7;              // 0 or 1
    const int t = threadIdx.x & 127;
    const int row = blockIdx.x * 2 + half;
    const long base = (long)row * DM + 4 * t;

    const float4 xv = *(const float4*)(x + base);
    const float4 ov = *(const float4*)(o + base);
    const float v0 = xv.x + ov.x, v1 = xv.y + ov.y;
    const float v2 = xv.z + ov.z, v3 = xv.w + ov.w;
    float s = v0 + v1 + v2 + v3;
    float sq = v0 * v0 + v1 * v1 + v2 * v2 + v3 * v3;
    #pragma unroll
    for (int off = 16; off; off >>= 1) {
        s  += __shfl_xor_sync(0xffffffffu, s, off);
        sq += __shfl_xor_sync(0xffffffffu, sq, off);
    }
    __shared__ float ss[8], sqs[8];
    __shared__ float mean_s[2], rstd_s[2];
    const int w = threadIdx.x >> 5;                 // 0..7 (warps never straddle rows)
    if ((threadIdx.x & 31) == 0) { ss[w] = s; sqs[w] = sq; }
    __syncthreads();
    if (t == 0) {
        const int wb = half * 4;
        const float s1 = ss[wb] + ss[wb + 1] + ss[wb + 2] + ss[wb + 3];
        const float s2 = sqs[wb] + sqs[wb + 1] + sqs[wb + 2] + sqs[wb + 3];
        const float m = s1 / (float)DM;
        mean_s[half] = m;
        rstd_s[half] = rsqrtf(s2 / (float)DM - m * m + 1e-5f);
    }
    __syncthreads();
    const float m = mean_s[half], r = rstd_s[half];
    const float4 scv = *(const float4*)(sc + 4 * t);
    const float4 biv = *(const float4*)(bi + 4 * t);
    float4 y;
    y.x = (v0 - m) * r * scv.x + biv.x;
    y.y = (v1 - m) * r * scv.y + biv.y;
    y.z = (v2 - m) * r * scv.z + biv.z;
    y.w = (v3 - m) * r * scv.w + biv.w;
    *(float4*)(x + base) = y;
    *(__half2*)(xh + base)     = __floats2half2_rn(y.x, y.y);
    *(__half2*)(xh + base + 2) = __floats2half2_rn(y.z, y.w);
}

// ---------------------------------------------------------------------------
extern "C" void kernel_launch(void* const* d_in, const int* in_sizes, int n_in,
                              void* d_out, int out_size) {
    const float* src   = (const float*)d_in[0];
    const float* qkv_w = (const float*)d_in[2];
    const float* qkv_b = (const float*)d_in[3];
    const float* out_w = (const float*)d_in[4];
    const float* out_b = (const float*)d_in[5];
    const float* ln1_s = (const float*)d_in[6];
    const float* ln1_b = (const float*)d_in[7];
    const float* w1    = (const float*)d_in[8];
    const float* b1    = (const float*)d_in[9];
    const float* w2    = (const float*)d_in[10];
    const float* b2    = (const float*)d_in[11];
    const float* ln2_s = (const float*)d_in[12];
    const float* ln2_b = (const float*)d_in[13];

    float* x = (float*)d_out;

    float *dbuf;
    __half *qkvh, *xh, *oh, *hh, *wh;
    cudaGetSymbolAddress((void**)&qkvh, g_qkvh);
    cudaGetSymbolAddress((void**)&dbuf, g_d);
    cudaGetSymbolAddress((void**)&xh, g_xh);
    cudaGetSymbolAddress((void**)&oh, g_oh);
    cudaGetSymbolAddress((void**)&hh, g_hh);
    cudaGetSymbolAddress((void**)&wh, g_wh);

    cudaFuncSetAttribute(gemm_tc<0,1,512,1536>, cudaFuncAttributeMaxDynamicSharedMemorySize, SMEMB);
    cudaFuncSetAttribute(gemm_tc<0,0,512,512>,  cudaFuncAttributeMaxDynamicSharedMemorySize, SMEMB);
    cudaFuncSetAttribute(gemm_tc<1,1,512,2048>, cudaFuncAttributeMaxDynamicSharedMemorySize, SMEMB);
    cudaFuncSetAttribute(gemm_tc<0,0,2048,512>, cudaFuncAttributeMaxDynamicSharedMemorySize, SMEMB);
    cudaFuncSetAttribute(attn_mma, cudaFuncAttributeMaxDynamicSharedMemorySize, ATT_SMEM);

    copy_conv<<<(ROWS*DM/4 + 255)/256, 256>>>(src, x, xh, ROWS*DM/4);                  // 1
    conv_all<<<(W_TOTAL/4 + 255)/256, 256>>>(qkv_w, out_w, w1, w2, wh);                // 2

    for (int l = 0; l < 2; l++) {
        gemm_tc<0,1,512,1536><<<dim3(12, 64), 128, SMEMB>>>(                           // 3
            xh, wh + OFF_QKV + (size_t)l*1536*512,
            qkv_b + (size_t)l*1536, nullptr, qkvh);

        attn_mma<<<dim3(SEQ/64, NH, BATCH), 256, ATT_SMEM>>>(qkvh, oh);                // 4

        gemm_tc<0,0,512,512><<<dim3(4, 64), 128, SMEMB>>>(
            oh, wh + OFF_OUT + (size_t)l*512*512,
            out_b + (size_t)l*512, dbuf, nullptr);

        add_ln_kernel<<<ROWS/2, 256>>>(x, dbuf, ln1_s + l*DM, ln1_b + l*DM, xh);

        gemm_tc<1,1,512,2048><<<dim3(16, 64), 128, SMEMB>>>(
            xh, wh + OFF_W1 + (size_t)l*2048*512,
            b1 + (size_t)l*2048, nullptr, hh);

        gemm_tc<0,0,2048,512><<<dim3(4, 64), 128, SMEMB>>>(
            hh, wh + OFF_W2 + (size_t)l*512*2048,
            b2 + (size_t)l*512, dbuf, nullptr);

        add_ln_kernel<<<ROWS/2, 256>>>(x, dbuf, ln2_s + l*DM, ln2_b + l*DM, xh);
    }
}

// round 17
// speedup vs baseline: 1.0577x; 1.0577x over previous
#include <cuda_runtime.h>
#include <cuda_fp16.h>
#include <math.h>
#include <stdint.h>

#define SEQ 2048
#define DM 512
#define NH 8
#define DH 64
#define DFF 2048
#define BATCH 4
#define ROWS (BATCH * SEQ)   // 8192

// ---------------- device scratch (no allocation allowed) -------------------
__device__ __half g_qkvh[(size_t)ROWS * 3 * DM];
__device__ float g_d[(size_t)ROWS * DM];
__device__ __half g_xh[(size_t)ROWS * DM];
__device__ __half g_oh[(size_t)ROWS * DM];
__device__ __half g_hh[(size_t)ROWS * DFF];
#define W_TOTAL 6291456
__device__ __half g_wh[W_TOTAL];
#define OFF_QKV 0
#define OFF_OUT (2 * 1536 * 512)
#define OFF_W1  (OFF_OUT + 2 * 512 * 512)
#define OFF_W2  (OFF_W1 + 2 * 2048 * 512)

// ---------------------------------------------------------------------------
// helpers
// ---------------------------------------------------------------------------
__device__ __forceinline__ void cp16(uint32_t saddr, const void* g) {
    asm volatile("cp.async.cg.shared.global [%0], [%1], 16;" :: "r"(saddr), "l"(g));
}
__device__ __forceinline__ void cp16z(uint32_t saddr, const void* g, int sz) {
    asm volatile("cp.async.cg.shared.global [%0], [%1], 16, %2;"
                 :: "r"(saddr), "l"(g), "r"(sz));
}
__device__ __forceinline__ void ldsm_x4(uint32_t* r, uint32_t a) {
    asm volatile("ldmatrix.sync.aligned.m8n8.x4.shared.b16 {%0,%1,%2,%3}, [%4];"
                 : "=r"(r[0]), "=r"(r[1]), "=r"(r[2]), "=r"(r[3]) : "r"(a));
}
__device__ __forceinline__ void ldsm_x4_t(uint32_t* r, uint32_t a) {
    asm volatile("ldmatrix.sync.aligned.m8n8.x4.trans.shared.b16 {%0,%1,%2,%3}, [%4];"
                 : "=r"(r[0]), "=r"(r[1]), "=r"(r[2]), "=r"(r[3]) : "r"(a));
}
__device__ __forceinline__ void mma_f16(float* d, const uint32_t* a, const uint32_t* b) {
    asm volatile("mma.sync.aligned.m16n8k16.row.col.f32.f16.f16.f32 "
                 "{%0,%1,%2,%3}, {%4,%5,%6,%7}, {%8,%9}, {%0,%1,%2,%3};"
                 : "+f"(d[0]), "+f"(d[1]), "+f"(d[2]), "+f"(d[3])
                 : "r"(a[0]), "r"(a[1]), "r"(a[2]), "r"(a[3]), "r"(b[0]), "r"(b[1]));
}
#define SWZ(bo) ((bo) ^ (((bo) >> 3) & 0x70))

// ---------------------------------------------------------------------------
// conversion kernels
// ---------------------------------------------------------------------------
__global__ void conv_all(const float* __restrict__ qkv_w, const float* __restrict__ out_w,
                         const float* __restrict__ w1, const float* __restrict__ w2,
                         __half* __restrict__ dst) {
    const int i = blockIdx.x * blockDim.x + threadIdx.x;
    if (i >= W_TOTAL / 4) return;
    const int e = i * 4;
    const float* src;
    int local;
    if (e < OFF_OUT)      { src = qkv_w; local = e; }
    else if (e < OFF_W1)  { src = out_w; local = e - OFF_OUT; }
    else if (e < OFF_W2)  { src = w1;    local = e - OFF_W1; }
    else                  { src = w2;    local = e - OFF_W2; }
    const float4 v = *(const float4*)(src + local);
    ((__half2*)dst)[2 * i]     = __floats2half2_rn(v.x, v.y);
    ((__half2*)dst)[2 * i + 1] = __floats2half2_rn(v.z, v.w);
}

__global__ void copy_conv(const float* __restrict__ src, float* __restrict__ x,
                          __half* __restrict__ xh, int n4) {
    const int i = blockIdx.x * blockDim.x + threadIdx.x;
    if (i >= n4) return;
    const float4 v = ((const float4*)src)[i];
    ((float4*)x)[i] = v;
    ((__half2*)xh)[2 * i]     = __floats2half2_rn(v.x, v.y);
    ((__half2*)xh)[2 * i + 1] = __floats2half2_rn(v.z, v.w);
}

// ---------------------------------------------------------------------------
// GEMM (unchanged): plain fp16, 128x128 block tile, BK=64, SW128, 128 thr.
// ---------------------------------------------------------------------------
#define PLANEB 16384
#define BUFB (2 * PLANEB)
#define SMEMB (2 * BUFB)

template<int RELU, int HALF_OUT, int K, int N>
__global__ __launch_bounds__(128)
void gemm_tc(const __half* __restrict__ Xh, const __half* __restrict__ Wh,
             const float* __restrict__ bias, float* __restrict__ Yf,
             __half* __restrict__ Yh) {
    extern __shared__ __align__(1024) char smc[];
    const uint32_t sb = (uint32_t)__cvta_generic_to_shared(smc);

    const int tid = threadIdx.x;
    const int lane = tid & 31, warp = tid >> 5;
    const int wm = warp & 1, wn = warp >> 1;
    const int g = lane >> 2, tig = lane & 3;
    const int m0 = blockIdx.y * 128, n0 = blockIdx.x * 128;

    float acc[4][8][4] = {};
    constexpr int KT = K >> 6;

    const int row0 = tid >> 3, ch = tid & 7;
    const __half* gp0 = Xh + (size_t)(m0 + row0) * K + ch * 8;
    const __half* gp1 = Wh + (size_t)(n0 + row0) * K + ch * 8;
    const uint32_t srow = SWZ((uint32_t)(row0 * 128 + ch * 16));

    const int lrow = lane & 15;
    const uint32_t kbase = ((uint32_t)((lane >> 4) << 4)) ^ ((uint32_t)((lrow & 7) << 4));
    const uint32_t aoff = sb + (uint32_t)((wm * 64 + lrow) * 128);
    const uint32_t boff = sb + (uint32_t)((wn * 64 + lrow) * 128) + (uint32_t)PLANEB;

#define STAGE2(SBUF) do {                                                      \
    _Pragma("unroll")                                                          \
    for (int r_ = 0; r_ < 8; r_++) {                                           \
        cp16((SBUF) + srow + r_ * 2048,          gp0 + r_ * 16 * K);           \
        cp16((SBUF) + PLANEB + srow + r_ * 2048, gp1 + r_ * 16 * K);           \
    }                                                                          \
    asm volatile("cp.async.commit_group;");                                    \
    gp0 += 64; gp1 += 64;                                                      \
} while (0)

#define KTILE(BOFS) do {                                                       \
    _Pragma("unroll")                                                          \
    for (int ks = 0; ks < 4; ks++) {                                           \
        const uint32_t kq = ((uint32_t)(ks * 32)) ^ kbase;                     \
        uint32_t ah[4][4], bh[8][2];                                           \
        _Pragma("unroll")                                                      \
        for (int i = 0; i < 4; i++)                                            \
            ldsm_x4(ah[i], aoff + (BOFS) + i * 2048 + kq);                     \
        _Pragma("unroll")                                                      \
        for (int jp = 0; jp < 4; jp++) {                                       \
            uint32_t th[4];                                                    \
            ldsm_x4(th, boff + (BOFS) + jp * 2048 + kq);                       \
            bh[jp * 2][0] = th[0]; bh[jp * 2 + 1][0] = th[1];                  \
            bh[jp * 2][1] = th[2]; bh[jp * 2 + 1][1] = th[3];                  \
        }                                                                      \
        _Pragma("unroll")                                                      \
        for (int i = 0; i < 4; i++)                                            \
            _Pragma("unroll")                                                  \
            for (int j = 0; j < 8; j++)                                        \
                mma_f16(acc[i][j], ah[i], bh[j]);                              \
    }                                                                          \
} while (0)

    STAGE2(sb);

    #pragma unroll 1
    for (int kt = 0; kt < KT; kt += 2) {
        asm volatile("cp.async.wait_group 0;");
        __syncthreads();
        if (kt + 1 < KT) STAGE2(sb + BUFB);
        KTILE(0u);

        asm volatile("cp.async.wait_group 0;");
        __syncthreads();
        if (kt + 2 < KT) STAGE2(sb);
        KTILE((uint32_t)BUFB);
    }
#undef STAGE2
#undef KTILE

    #pragma unroll
    for (int i = 0; i < 4; i++) {
        const int row0e = m0 + wm * 64 + i * 16 + g;
        #pragma unroll
        for (int j = 0; j < 8; j++) {
            const int col = n0 + wn * 64 + j * 8 + 2 * tig;
            const float2 bv = *(const float2*)(bias + col);
            float2 v0 = { acc[i][j][0] + bv.x, acc[i][j][1] + bv.y };
            float2 v1 = { acc[i][j][2] + bv.x, acc[i][j][3] + bv.y };
            if (RELU) {
                v0.x = fmaxf(v0.x, 0.f); v0.y = fmaxf(v0.y, 0.f);
                v1.x = fmaxf(v1.x, 0.f); v1.y = fmaxf(v1.y, 0.f);
            }
            if (HALF_OUT) {
                *(__half2*)(Yh + (size_t)row0e * N + col) = __floats2half2_rn(v0.x, v0.y);
                *(__half2*)(Yh + (size_t)(row0e + 8) * N + col) = __floats2half2_rn(v1.x, v1.y);
            } else {
                *(float2*)(Yf + (size_t)row0e * N + col) = v0;
                *(float2*)(Yf + (size_t)(row0e + 8) * N + col) = v1;
            }
        }
    }
}

// ---------------------------------------------------------------------------
// Tensor-core log-sparse attention (R15 version): 32 q/block, fp16 qkv input,
// cp.async zfill staging, 3 CTAs/SM.
// ---------------------------------------------------------------------------
#define ATT_QS  0
#define ATT_KS  4096
#define ATT_VS  20480
#define ATT_PS  36864
#define ATT_OEX 45056
#define ATT_MX4 53248
#define ATT_SM4 53760
#define ATT_EXM 54272
#define ATT_EXS 54400
#define ATT_EXP 54528
#define ATT_SMEM 55040

__global__ __launch_bounds__(256, 3)
void attn_mma(const __half* __restrict__ qkv, __half* __restrict__ oh) {
    extern __shared__ __align__(1024) char smc[];
    const uint32_t sb = (uint32_t)__cvta_generic_to_shared(smc);

    const int q0 = blockIdx.x * 32;
    const int h = blockIdx.y, b = blockIdx.z;
    const int tid = threadIdx.x, lane = tid & 31, warp = tid >> 5;
    const int wq = warp & 1, wk = warp >> 1;
    const int g = lane >> 2, tig = lane & 3, lrow = lane & 15;

    const __half* base = qkv + (size_t)(b * SEQ) * 1536;

    // ---- async staging: Q (1 chunk), K (4), V (4) per thread ----
    {
        const int row = tid >> 3, ch = tid & 7;
        cp16(sb + ATT_QS + SWZ((uint32_t)(row * 128 + ch * 16)),
             base + (size_t)(q0 + row) * 1536 + h * 64 + ch * 8);
        #pragma unroll
        for (int r_ = 0; r_ < 4; r_++) {
            const int rr = row + r_ * 32;
            const int j = q0 - 64 + rr;
            const int valid = (j >= 0 && rr < 96) ? 16 : 0;
            const size_t jc = (size_t)(valid ? j : 0);
            const uint32_t so = SWZ((uint32_t)(rr * 128 + ch * 16));
            cp16z(sb + ATT_KS + so, base + jc * 1536 + 512 + h * 64 + ch * 8, valid);
            cp16z(sb + ATT_VS + so, base + jc * 1536 + 1024 + h * 64 + ch * 8, valid);
        }
        asm volatile("cp.async.commit_group;");
    }

    // ---- extras raw scores from gmem (overlaps with staging) ----
    {
        float* EXM = (float*)(smc + ATT_EXM);
        float* EXPS = (float*)(smc + ATT_EXP);
        const int te = lane >> 3, g8 = lane & 7;
        #pragma unroll
        for (int c = 0; c < 4; c++) {
            const int qi = warp * 4 + c;
            const int i = q0 + qi;
            const int ne = (i >= 128) + (i >= 256) + (i >= 512) + (i >= 1024);
            float pt = 0.f;
            if (te < ne) {
                const int j = i - (128 << te);
                const uint4 kraw = *(const uint4*)(base + (size_t)j * 1536 + 512 + h * 64 + g8 * 8);
                const uint4 qraw = *(const uint4*)(base + (size_t)i * 1536 + h * 64 + g8 * 8);
                const __half2* k2 = (const __half2*)&kraw;
                const __half2* q2 = (const __half2*)&qraw;
                #pragma unroll
                for (int u = 0; u < 4; u++) {
                    const float2 kf = __half22float2(k2[u]);
                    const float2 qf = __half22float2(q2[u]);
                    pt += qf.x * kf.x + qf.y * kf.y;
                }
            }
            pt += __shfl_xor_sync(~0u, pt, 1);
            pt += __shfl_xor_sync(~0u, pt, 2);
            pt += __shfl_xor_sync(~0u, pt, 4);
            pt *= 0.125f;
            const float p0 = __shfl_sync(~0u, pt, 0);
            const float p1 = __shfl_sync(~0u, pt, 8);
            const float p2 = __shfl_sync(~0u, pt, 16);
            const float p3 = __shfl_sync(~0u, pt, 24);
            float mex = -INFINITY;
            if (ne > 0) mex = p0;
            if (ne > 1) mex = fmaxf(mex, p1);
            if (ne > 2) mex = fmaxf(mex, p2);
            if (ne > 3) mex = fmaxf(mex, p3);
            if (lane == 0) {
                EXM[qi] = mex;
                EXPS[qi * 4 + 0] = p0; EXPS[qi * 4 + 1] = p1;
                EXPS[qi * 4 + 2] = p2; EXPS[qi * 4 + 3] = p3;
            }
        }
    }
    asm volatile("cp.async.wait_group 0;");
    __syncthreads();

    // ---- S = Q @ K^T (window) ----
    float S[4][4] = {};
    const uint32_t kbase = ((uint32_t)((lane >> 4) << 4)) ^ ((uint32_t)((lrow & 7) << 4));
    {
        const uint32_t qa = sb + ATT_QS + (uint32_t)((wq * 16 + lrow) * 128);
        const uint32_t kb = sb + ATT_KS + (uint32_t)((wk * 32 + lrow) * 128);
        #pragma unroll
        for (int ks = 0; ks < 4; ks++) {
            const uint32_t kq = ((uint32_t)(ks * 32)) ^ kbase;
            uint32_t A[4], th[4], B[4][2];
            ldsm_x4(A, qa + kq);
            ldsm_x4(th, kb + kq);
            B[0][0] = th[0]; B[1][0] = th[1]; B[0][1] = th[2]; B[1][1] = th[3];
            ldsm_x4(th, kb + 2048 + kq);
            B[2][0] = th[0]; B[3][0] = th[1]; B[2][1] = th[2]; B[3][1] = th[3];
            #pragma unroll
            for (int j = 0; j < 4; j++) mma_f16(S[j], A, B[j]);
        }
    }

    // ---- mask + scale + partial row max ----
    const int r0 = wq * 16 + g, r1 = r0 + 8;
    const int cmin = 64 - q0;
    float m0 = -INFINITY, m1 = -INFINITY;
    #pragma unroll
    for (int j = 0; j < 4; j++) {
        const int col0 = wk * 32 + j * 8 + 2 * tig;
        const int col1 = col0 + 1;
        S[j][0] = (col0 >= r0 && col0 <= r0 + 64 && col0 >= cmin) ? S[j][0] * 0.125f : -INFINITY;
        S[j][1] = (col1 >= r0 && col1 <= r0 + 64 && col1 >= cmin) ? S[j][1] * 0.125f : -INFINITY;
        S[j][2] = (col0 >= r1 && col0 <= r1 + 64 && col0 >= cmin) ? S[j][2] * 0.125f : -INFINITY;
        S[j][3] = (col1 >= r1 && col1 <= r1 + 64 && col1 >= cmin) ? S[j][3] * 0.125f : -INFINITY;
        m0 = fmaxf(m0, fmaxf(S[j][0], S[j][1]));
        m1 = fmaxf(m1, fmaxf(S[j][2], S[j][3]));
    }
    m0 = fmaxf(m0, __shfl_xor_sync(~0u, m0, 1)); m0 = fmaxf(m0, __shfl_xor_sync(~0u, m0, 2));
    m1 = fmaxf(m1, __shfl_xor_sync(~0u, m1, 1)); m1 = fmaxf(m1, __shfl_xor_sync(~0u, m1, 2));
    {
        float* MX4 = (float*)(smc + ATT_MX4);
        if (tig == 0) { MX4[r0 * 4 + wk] = m0; MX4[r1 * 4 + wk] = m1; }
    }
    __syncthreads();

    // ---- final row max, exp, partial sums, store P; extras exp ----
    {
        float* MX4 = (float*)(smc + ATT_MX4);
        float* SM4 = (float*)(smc + ATT_SM4);
        float* EXM = (float*)(smc + ATT_EXM);
        const float mxf0 = fmaxf(fmaxf(fmaxf(MX4[r0 * 4], MX4[r0 * 4 + 1]),
                                       fmaxf(MX4[r0 * 4 + 2], MX4[r0 * 4 + 3])), EXM[r0]);
        const float mxf1 = fmaxf(fmaxf(fmaxf(MX4[r1 * 4], MX4[r1 * 4 + 1]),
                                       fmaxf(MX4[r1 * 4 + 2], MX4[r1 * 4 + 3])), EXM[r1]);
        float s0 = 0.f, s1 = 0.f;
        #pragma unroll
        for (int j = 0; j < 4; j++) {
            const float e0 = __expf(S[j][0] - mxf0), e1 = __expf(S[j][1] - mxf0);
            const float e2 = __expf(S[j][2] - mxf1), e3 = __expf(S[j][3] - mxf1);
            s0 += e0 + e1; s1 += e2 + e3;
            const int col0 = wk * 32 + j * 8 + 2 * tig;
            char* ps = smc + ATT_PS + (col0 >> 6) * 4096;
            const int kc2 = (col0 & 63) * 2;
            *(__half2*)(ps + SWZ((uint32_t)(r0 * 128 + kc2))) = __floats2half2_rn(e0, e1);
            *(__half2*)(ps + SWZ((uint32_t)(r1 * 128 + kc2))) = __floats2half2_rn(e2, e3);
        }
        s0 += __shfl_xor_sync(~0u, s0, 1); s0 += __shfl_xor_sync(~0u, s0, 2);
        s1 += __shfl_xor_sync(~0u, s1, 1); s1 += __shfl_xor_sync(~0u, s1, 2);
        if (tig == 0) { SM4[r0 * 4 + wk] = s0; SM4[r1 * 4 + wk] = s1; }

        float* EXS = (float*)(smc + ATT_EXS);
        float* EXPS = (float*)(smc + ATT_EXP);
        #pragma unroll
        for (int c = 0; c < 4; c++) {
            const int qi = warp * 4 + c;
            const int i = q0 + qi;
            const int ne = (i >= 128) + (i >= 256) + (i >= 512) + (i >= 1024);
            const float mxfq = fmaxf(fmaxf(fmaxf(MX4[qi * 4], MX4[qi * 4 + 1]),
                                           fmaxf(MX4[qi * 4 + 2], MX4[qi * 4 + 3])), EXM[qi]);
            float e = 0.f;
            if (lane < 4) {
                e = (lane < ne) ? __expf(EXPS[qi * 4 + lane] - mxfq) : 0.f;
                EXPS[qi * 4 + lane] = e;
            }
            e += __shfl_xor_sync(~0u, e, 1);
            e += __shfl_xor_sync(~0u, e, 2);
            if (lane == 0) EXS[qi] = e;
        }
    }
    __syncthreads();

    // ---- extras output Oex ----
    {
        float* OEX = (float*)(smc + ATT_OEX);
        float* EXPS = (float*)(smc + ATT_EXP);
        #pragma unroll
        for (int c = 0; c < 4; c++) {
            const int qi = warp * 4 + c;
            const int i = q0 + qi;
            const int ne = (i >= 128) + (i >= 256) + (i >= 512) + (i >= 1024);
            float2 a = {0.f, 0.f};
            #pragma unroll
            for (int t = 0; t < 4; t++) {
                if (t < ne) {
                    const int j = i - (128 << t);
                    const float2 vf = __half22float2(
                        *(const __half2*)(base + (size_t)j * 1536 + 1024 + h * 64 + 2 * lane));
                    const float wgt = EXPS[qi * 4 + t];
                    a.x += wgt * vf.x;
                    a.y += wgt * vf.y;
                }
            }
            *(float2*)(OEX + qi * 64 + 2 * lane) = a;
        }
    }
    // ---- O = P @ V ----
    float O[2][4] = {};
    {
        const uint32_t pa = sb + ATT_PS + (uint32_t)((wq * 16 + lrow) * 128);
        const uint32_t vb = sb + ATT_VS + (uint32_t)(lrow * 128);
        const uint32_t vdim = ((uint32_t)(wk * 32 + ((lane >> 4) << 4)))
                            ^ ((uint32_t)((lrow & 7) << 4));
        #pragma unroll
        for (int ks = 0; ks < 8; ks++) {
            uint32_t A[4], th[4];
            const uint32_t kq = ((uint32_t)((ks & 3) * 32)) ^ kbase;
            ldsm_x4(A, pa + (ks >> 2) * 4096 + kq);
            ldsm_x4_t(th, vb + ks * 2048 + vdim);
            uint32_t B0[2] = { th[0], th[1] };
            uint32_t B1[2] = { th[2], th[3] };
            mma_f16(O[0], A, B0);
            mma_f16(O[1], A, B1);
        }
    }
    __syncthreads();

    // ---- epilogue ----
    {
        float* SM4 = (float*)(smc + ATT_SM4);
        float* EXS = (float*)(smc + ATT_EXS);
        float* OEX = (float*)(smc + ATT_OEX);
        const float inv0 = 1.f / (SM4[r0 * 4] + SM4[r0 * 4 + 1] + SM4[r0 * 4 + 2] +
                                  SM4[r0 * 4 + 3] + EXS[r0]);
        const float inv1 = 1.f / (SM4[r1 * 4] + SM4[r1 * 4 + 1] + SM4[r1 * 4 + 2] +
                                  SM4[r1 * 4 + 3] + EXS[r1]);
        #pragma unroll
        for (int j = 0; j < 2; j++) {
            const int col0 = wk * 16 + j * 8 + 2 * tig;
            const float2 ex0 = *(const float2*)(OEX + r0 * 64 + col0);
            const float2 ex1 = *(const float2*)(OEX + r1 * 64 + col0);
            const __half2 h0 = __floats2half2_rn((O[j][0] + ex0.x) * inv0,
                                                 (O[j][1] + ex0.y) * inv0);
            const __half2 h1 = __floats2half2_rn((O[j][2] + ex1.x) * inv1,
                                                 (O[j][3] + ex1.y) * inv1);
            *(__half2*)(oh + (size_t)(b * SEQ + q0 + r0) * DM + h * 64 + col0) = h0;
            *(__half2*)(oh + (size_t)(b * SEQ + q0 + r1) * DM + h * 64 + col0) = h1;
        }
    }
}

// ---------------------------------------------------------------------------
// x = LayerNorm(x + d) * scale + bias; emits fp16 copy. 2 rows per block.
// ---------------------------------------------------------------------------
__global__ __launch_bounds__(256)
void add_ln_kernel(float* __restrict__ x, const float* __restrict__ o,
                   const float* __restrict__ sc, const float* __restrict__ bi,
                   __half* __restrict__ xh) {
    const int half = threadIdx.x >> 7;
    const int t = threadIdx.x & 127;
    const int row = blockIdx.x * 2 + half;
    const long base = (long)row * DM + 4 * t;

    const float4 xv = *(const float4*)(x + base);
    const float4 ov = *(const float4*)(o + base);
    const float v0 = xv.x + ov.x, v1 = xv.y + ov.y;
    const float v2 = xv.z + ov.z, v3 = xv.w + ov.w;
    float s = v0 + v1 + v2 + v3;
    float sq = v0 * v0 + v1 * v1 + v2 * v2 + v3 * v3;
    #pragma unroll
    for (int off = 16; off; off >>= 1) {
        s  += __shfl_xor_sync(0xffffffffu, s, off);
        sq += __shfl_xor_sync(0xffffffffu, sq, off);
    }
    __shared__ float ss[8], sqs[8];
    __shared__ float mean_s[2], rstd_s[2];
    const int w = threadIdx.x >> 5;
    if ((threadIdx.x & 31) == 0) { ss[w] = s; sqs[w] = sq; }
    __syncthreads();
    if (t == 0) {
        const int wb = half * 4;
        const float s1 = ss[wb] + ss[wb + 1] + ss[wb + 2] + ss[wb + 3];
        const float s2 = sqs[wb] + sqs[wb + 1] + sqs[wb + 2] + sqs[wb + 3];
        const float m = s1 / (float)DM;
        mean_s[half] = m;
        rstd_s[half] = rsqrtf(s2 / (float)DM - m * m + 1e-5f);
    }
    __syncthreads();
    const float m = mean_s[half], r = rstd_s[half];
    const float4 scv = *(const float4*)(sc + 4 * t);
    const float4 biv = *(const float4*)(bi + 4 * t);
    float4 y;
    y.x = (v0 - m) * r * scv.x + biv.x;
    y.y = (v1 - m) * r * scv.y + biv.y;
    y.z = (v2 - m) * r * scv.z + biv.z;
    y.w = (v3 - m) * r * scv.w + biv.w;
    *(float4*)(x + base) = y;
    *(__half2*)(xh + base)     = __floats2half2_rn(y.x, y.y);
    *(__half2*)(xh + base + 2) = __floats2half2_rn(y.z, y.w);
}

// ---------------------------------------------------------------------------
extern "C" void kernel_launch(void* const* d_in, const int* in_sizes, int n_in,
                              void* d_out, int out_size) {
    const float* src   = (const float*)d_in[0];
    const float* qkv_w = (const float*)d_in[2];
    const float* qkv_b = (const float*)d_in[3];
    const float* out_w = (const float*)d_in[4];
    const float* out_b = (const float*)d_in[5];
    const float* ln1_s = (const float*)d_in[6];
    const float* ln1_b = (const float*)d_in[7];
    const float* w1    = (const float*)d_in[8];
    const float* b1    = (const float*)d_in[9];
    const float* w2    = (const float*)d_in[10];
    const float* b2    = (const float*)d_in[11];
    const float* ln2_s = (const float*)d_in[12];
    const float* ln2_b = (const float*)d_in[13];

    float* x = (float*)d_out;

    float *dbuf;
    __half *qkvh, *xh, *oh, *hh, *wh;
    cudaGetSymbolAddress((void**)&qkvh, g_qkvh);
    cudaGetSymbolAddress((void**)&dbuf, g_d);
    cudaGetSymbolAddress((void**)&xh, g_xh);
    cudaGetSymbolAddress((void**)&oh, g_oh);
    cudaGetSymbolAddress((void**)&hh, g_hh);
    cudaGetSymbolAddress((void**)&wh, g_wh);

    cudaFuncSetAttribute(gemm_tc<0,1,512,1536>, cudaFuncAttributeMaxDynamicSharedMemorySize, SMEMB);
    cudaFuncSetAttribute(gemm_tc<0,0,512,512>,  cudaFuncAttributeMaxDynamicSharedMemorySize, SMEMB);
    cudaFuncSetAttribute(gemm_tc<1,1,512,2048>, cudaFuncAttributeMaxDynamicSharedMemorySize, SMEMB);
    cudaFuncSetAttribute(gemm_tc<0,0,2048,512>, cudaFuncAttributeMaxDynamicSharedMemorySize, SMEMB);
    cudaFuncSetAttribute(attn_mma, cudaFuncAttributeMaxDynamicSharedMemorySize, ATT_SMEM);

    copy_conv<<<(ROWS*DM/4 + 255)/256, 256>>>(src, x, xh, ROWS*DM/4);                  // 1
    conv_all<<<(W_TOTAL/4 + 255)/256, 256>>>(qkv_w, out_w, w1, w2, wh);                // 2

    for (int l = 0; l < 2; l++) {
        gemm_tc<0,1,512,1536><<<dim3(12, 64), 128, SMEMB>>>(                           // 3
            xh, wh + OFF_QKV + (size_t)l*1536*512,
            qkv_b + (size_t)l*1536, nullptr, qkvh);

        attn_mma<<<dim3(SEQ/32, NH, BATCH), 256, ATT_SMEM>>>(qkvh, oh);                // 4

        gemm_tc<0,0,512,512><<<dim3(4, 64), 128, SMEMB>>>(
            oh, wh + OFF_OUT + (size_t)l*512*512,
            out_b + (size_t)l*512, dbuf, nullptr);

        add_ln_kernel<<<ROWS/2, 256>>>(x, dbuf, ln1_s + l*DM, ln1_b + l*DM, xh);

        gemm_tc<1,1,512,2048><<<dim3(16, 64), 128, SMEMB>>>(
            xh, wh + OFF_W1 + (size_t)l*2048*512,
            b1 + (size_t)l*2048, nullptr, hh);

        gemm_tc<0,0,2048,512><<<dim3(4, 64), 128, SMEMB>>>(
            hh, wh + OFF_W2 + (size_t)l*512*2048,
            b2 + (size_t)l*512, dbuf, nullptr);

        add_ln_kernel<<<ROWS/2, 256>>>(x, dbuf, ln2_s + l*DM, ln2_b + l*DM, xh);
    }
}